// round 15
// baseline (speedup 1.0000x reference)
#include <cuda_runtime.h>
#include <cuda_bf16.h>
#include <stdint.h>
#include <math.h>

// Problem constants
#define NN 50000
#define EE 800000
#define ET (EE + NN)          // edges incl. self loops
#define GG 256
#define FF 9
#define GF 187
#define HH 4
#define O1 64
#define O2 128
#define HO1 (HH * O1)         // 256
#define HO2 (HH * O2)         // 512
#define BN_EPS 1e-5f
#define SM_EPS 1e-16f
#define SCAN_T 512
#define SCAN_NB ((NN + SCAN_T - 1) / SCAN_T)   // 98

typedef __nv_bfloat16  bf16;
typedef __nv_bfloat162 bf162;

// ---------------- scratch (device globals; no allocation allowed) -------------
__device__ bf16  g_xl1[(size_t)NN * HO1];
__device__ bf16  g_xr1[(size_t)NN * HO1];
__device__ bf16  g_h1 [(size_t)NN * HO1];
__device__ bf16  g_xl2[(size_t)NN * HO2];
__device__ bf16  g_xr2[(size_t)NN * HO2];
__device__ bf16  g_wl2t[(size_t)HO2 * HO1];   // [N=512][K=256] transposed bf16
__device__ bf16  g_wr2t[(size_t)HO2 * HO1];
__device__ float g_pooled[(size_t)GG * HO2];
__device__ int   g_cnt[GG];
// CSR scratch (g_deg starts zeroed; every graph replay leaves it zeroed)
__device__ int g_deg[NN];
__device__ int g_rowptr[NN + 1];
__device__ int g_cursor[NN];
__device__ int g_bsum[SCAN_NB];
__device__ int g_csrc[ET];

// ---------------- fused prologue -----------------------------------------------
// transform1 batched 4 nodes/block (W1 rows register-resident, reused 4x).
#define NB_T1 ((NN + 3) / 4)          // 12500 blocks
#define NB_CW 512                     // per weight matrix
#define NB_CD ((EE + 255) / 256)      // 3125
#define NB_ZP ((GG * HO2 / 4 + 255) / 256)   // 128
#define NB_PRE (NB_T1 + 2 * NB_CW + NB_CD + NB_ZP)

__global__ void __launch_bounds__(256)
fused_pre(const float* __restrict__ x,
          const float* __restrict__ Wl1, const float* __restrict__ bl1,
          const float* __restrict__ Wr1, const float* __restrict__ br1,
          bf16* __restrict__ xl1, bf16* __restrict__ xr1,
          const float* __restrict__ Wl2, const float* __restrict__ Wr2,
          bf16* __restrict__ wl2t, bf16* __restrict__ wr2t,
          const int* __restrict__ ei, int* __restrict__ deg,
          float4* __restrict__ pooled, int* __restrict__ cnt) {
    int b = blockIdx.x, t = threadIdx.x;
    if (b < NB_T1) {
        // transform1: nodes 4b..4b+3, 256 output channels each
        __shared__ float sx[4][FF];
        int n0 = b * 4;
        if (t < 4 * FF) {
            int nn = t / FF, kk = t % FF;
            int n = n0 + nn;
            sx[nn][kk] = (n < NN) ? x[n * FF + kk] : 0.f;
        }
        float wl[FF], wr[FF];
#pragma unroll
        for (int k = 0; k < FF; k++) {
            wl[k] = Wl1[k * HO1 + t];
            wr[k] = Wr1[k * HO1 + t];
        }
        float bl = bl1[t], br = br1[t];
        __syncthreads();
#pragma unroll
        for (int nn = 0; nn < 4; nn++) {
            int n = n0 + nn;
            if (n >= NN) break;
            float al = bl, ar = br;
#pragma unroll
            for (int k = 0; k < FF; k++) {
                float xv = sx[nn][k];
                al += xv * wl[k];
                ar += xv * wr[k];
            }
            xl1[(size_t)n * HO1 + t] = __float2bfloat16(al);
            xr1[(size_t)n * HO1 + t] = __float2bfloat16(ar);
        }
    } else if (b < NB_T1 + 2 * NB_CW) {
        int bb = b - NB_T1;
        const float* W = (bb < NB_CW) ? Wl2 : Wr2;
        bf16* Wt       = (bb < NB_CW) ? wl2t : wr2t;
        int n = bb % NB_CW;
        Wt[(size_t)n * HO1 + t] = __float2bfloat16(W[(size_t)t * HO2 + n]);
    } else if (b < NB_T1 + 2 * NB_CW + NB_CD) {
        int e = (b - NB_T1 - 2 * NB_CW) * 256 + t;
        if (e < EE) atomicAdd(&deg[ei[EE + e]], 1);
    } else {
        int i = (b - NB_T1 - 2 * NB_CW - NB_CD) * 256 + t;
        if (i < GG * HO2 / 4) pooled[i] = make_float4(0.f, 0.f, 0.f, 0.f);
        if (i < GG) cnt[i] = 0;
    }
}

// ---------------- CSR scan/scatter ----------------------------------------------
__global__ void scan_local(int* __restrict__ deg, int* __restrict__ rowptr,
                           int* __restrict__ bsum) {
    __shared__ int s[SCAN_T];
    int i = blockIdx.x * SCAN_T + threadIdx.x;
    int v = 0;
    if (i < NN) { v = deg[i] + 1; deg[i] = 0; }
    s[threadIdx.x] = v;
    __syncthreads();
    for (int off = 1; off < SCAN_T; off <<= 1) {
        int t = (threadIdx.x >= off) ? s[threadIdx.x - off] : 0;
        __syncthreads();
        s[threadIdx.x] += t;
        __syncthreads();
    }
    if (i < NN) rowptr[i] = s[threadIdx.x] - v;   // exclusive
    if (threadIdx.x == SCAN_T - 1) bsum[blockIdx.x] = s[threadIdx.x];
}
__global__ void scan_add2(int* __restrict__ rowptr, const int* __restrict__ bsum,
                          int* __restrict__ cursor) {
    __shared__ int sb[SCAN_NB];
    __shared__ int off;
    int b = blockIdx.x, t = threadIdx.x;
    if (t < SCAN_NB) sb[t] = bsum[t];
    __syncthreads();
    if (t == 0) {
        int acc = 0;
        for (int i = 0; i < b; i++) acc += sb[i];
        off = acc;
    }
    __syncthreads();
    int i = b * SCAN_T + t;
    if (i < NN) {
        int r = rowptr[i] + off;
        rowptr[i] = r;
        cursor[i] = r;
    }
    if (i == 0) rowptr[NN] = ET;
}
__global__ void scatter_csr(const int* __restrict__ ei, int* __restrict__ cursor,
                            int* __restrict__ csrc) {
    int e = blockIdx.x * blockDim.x + threadIdx.x;
    if (e >= ET) return;
    int s, d;
    if (e < EE) { s = ei[e]; d = ei[EE + e]; }
    else        { s = d = e - EE; }
    int p = atomicAdd(&cursor[d], 1);
    csrc[p] = s;
}

// ---------------- fused GAT layer (R12 structure, LOCKED) -----------------------
__device__ __forceinline__ void cvt4(const uint2 r, float* f) {
    float2 t;
    t = __bfloat1622float2(*(const bf162*)&r.x); f[0] = t.x; f[1] = t.y;
    t = __bfloat1622float2(*(const bf162*)&r.y); f[2] = t.x; f[3] = t.y;
}

template <int EPL, int PARTS, int SEG, bool POOL>   // EPL floats/lane (4)
__global__ void __launch_bounds__(256)
gat_fused(const int* __restrict__ rowptr, const int* __restrict__ csrc,
          const bf16* __restrict__ xl, const bf16* __restrict__ xr,
          const float* __restrict__ att, const float* __restrict__ bias,
          const float* __restrict__ bng, const float* __restrict__ bnb,
          const float* __restrict__ bnm, const float* __restrict__ bnv,
          bf16* __restrict__ out, float* __restrict__ pooled,
          int* __restrict__ cnt, const int* __restrict__ batch) {
    const int SL = EPL * 32;              // slice elems per warp
    const int HO = SL * PARTS;            // full row length
    int gw   = blockIdx.x * 8 + (threadIdx.x >> 5);
    int node = gw / PARTS;
    int part = gw % PARTS;
    int lane = threadIdx.x & 31;
    if (node >= NN) return;
    int    cbase = part * SL + lane * EPL;
    size_t nb    = (size_t)node * HO + cbase;

    float xr_r[EPL], att_r[EPL], S[EPL], v[EPL];
    cvt4(*(const uint2*)(xr + nb), xr_r);
    {
        float4 u = *(const float4*)(att + cbase);
        att_r[0] = u.x; att_r[1] = u.y; att_r[2] = u.z; att_r[3] = u.w;
    }
#pragma unroll
    for (int r = 0; r < EPL; r++) S[r] = 0.f;
    float den = 0.f;

    int beg = __ldg(rowptr + node), end = __ldg(rowptr + node + 1);
    int sn = __ldg(csrc + beg);
    uint2 rawn = *(const uint2*)(xl + (size_t)sn * HO + cbase);

    for (int e = beg; e < end; e++) {
        cvt4(rawn, v);
        if (e + 1 < end) {
            sn = __ldg(csrc + e + 1);
            rawn = *(const uint2*)(xl + (size_t)sn * HO + cbase);
        }
        float a = 0.f;
#pragma unroll
        for (int r = 0; r < EPL; r++) {
            float t = v[r] + xr_r[r];
            t = fmaxf(t, 0.2f * t);                 // leaky_relu(0.2)
            a = fmaf(t, att_r[r], a);
        }
        // segmented butterfly over the SEG-lane head group
        a += __shfl_xor_sync(0xFFFFFFFFu, a, 1);
        a += __shfl_xor_sync(0xFFFFFFFFu, a, 2);
        a += __shfl_xor_sync(0xFFFFFFFFu, a, 4);
        if constexpr (SEG >= 16) a += __shfl_xor_sync(0xFFFFFFFFu, a, 8);
        if constexpr (SEG == 32) a += __shfl_xor_sync(0xFFFFFFFFu, a, 16);
        float w = __expf(a);                        // bounded logits: no max needed
        den += w;
#pragma unroll
        for (int r = 0; r < EPL; r++) S[r] = fmaf(w, v[r], S[r]);
    }

    float inv = 1.f / (den + SM_EPS);
    float o[EPL];
#pragma unroll
    for (int r = 0; r < EPL; r++) {
        int c = cbase + r;
        float y = S[r] * inv + __ldg(bias + c);
        y = __ldg(bng + c) * (y - __ldg(bnm + c)) * rsqrtf(__ldg(bnv + c) + BN_EPS)
            + __ldg(bnb + c);
        o[r] = fmaxf(y, 0.f);
    }

    if constexpr (POOL) {
        int g = __ldg(batch + node);
        atomicAdd((float4*)(pooled + (size_t)g * HO + cbase),
                  make_float4(o[0], o[1], o[2], o[3]));
        if (part == 0 && lane == 0) atomicAdd(&cnt[g], 1);
    } else {
        uint2 raw;
        *(bf162*)&raw.x = __floats2bfloat162_rn(o[0], o[1]);
        *(bf162*)&raw.y = __floats2bfloat162_rn(o[2], o[3]);
        *(uint2*)(out + nb) = raw;
    }
}

// ---------------- bf16 tensor-core GEMM (cp.async double-buffered, K-tile 64) ---
#define LDSH 72
__device__ __forceinline__ void cp16(uint32_t dst, const void* src) {
    asm volatile("cp.async.cg.shared.global [%0], [%1], 16;\n" :: "r"(dst), "l"(src));
}
__global__ void __launch_bounds__(256)
gemm_bf16(const bf16* __restrict__ A,
          const bf16* __restrict__ Wt0, const bf16* __restrict__ Wt1,
          const float* __restrict__ bias0, const float* __restrict__ bias1,
          bf16* __restrict__ C0, bf16* __restrict__ C1,
          int M, int N, int K) {
    __shared__ __align__(16) bf16 As[2][128 * LDSH];
    __shared__ __align__(16) bf16 Bs[2][128 * LDSH];
    const bf16*  Wt   = blockIdx.z ? Wt1   : Wt0;
    const float* bias = blockIdx.z ? bias1 : bias0;
    bf16*        C    = blockIdx.z ? C1    : C0;

    int tid = threadIdx.x, warp = tid >> 5, lane = tid & 31;
    int bm = blockIdx.x * 128, bn = blockIdx.y * 128;
    int wm = (warp >> 1) * 32, wn = (warp & 1) * 64;
    int idx = lane & 7;
    int a_row = wm + ((lane >> 3) & 1) * 8 + idx;
    int a_col = (lane >> 4) * 8;
    int b_row = wn + (lane >> 4) * 8 + idx;
    int b_col = ((lane >> 3) & 1) * 8;
    uint32_t aBase = (uint32_t)__cvta_generic_to_shared(&As[0][0]);
    uint32_t bBase = (uint32_t)__cvta_generic_to_shared(&Bs[0][0]);
    uint32_t aAddr = aBase + (a_row * LDSH + a_col) * 2;
    uint32_t bAddr = bBase + (b_row * LDSH + b_col) * 2;
    const uint32_t bufB = 128 * LDSH * 2;

    float acc[2][8][4];
#pragma unroll
    for (int i = 0; i < 2; i++)
#pragma unroll
        for (int j = 0; j < 8; j++)
#pragma unroll
            for (int q = 0; q < 4; q++) acc[i][j][q] = 0.f;

    int lr = tid >> 2;            // 0..63 (row within 64-row half)
    int lc0 = (tid & 3) * 16;     // 0,16,32,48

    const int NT = K / 64;        // 4 k-tiles of 64
    auto load_tile = [&](int buf, int k0) {
#pragma unroll
        for (int r = 0; r < 2; r++) {
            int row  = lr + r * 64;
            int grow = bm + row; if (grow > M - 1) grow = M - 1;
#pragma unroll
            for (int c = 0; c < 2; c++) {
                int col = lc0 + c * 8;
                cp16(aBase + buf * bufB + (row * LDSH + col) * 2,
                     A + (size_t)grow * K + k0 + col);
                cp16(bBase + buf * bufB + (row * LDSH + col) * 2,
                     Wt + (size_t)(bn + row) * K + k0 + col);
            }
        }
        asm volatile("cp.async.commit_group;\n");
    };

    load_tile(0, 0);
    for (int kt = 0; kt < NT; kt++) {
        if (kt + 1 < NT) {
            load_tile((kt + 1) & 1, (kt + 1) * 64);
            asm volatile("cp.async.wait_group 1;\n");
        } else {
            asm volatile("cp.async.wait_group 0;\n");
        }
        __syncthreads();
        int buf = kt & 1;
#pragma unroll
        for (int ks = 0; ks < 64; ks += 16) {
            uint32_t afr[2][4], bfr[4][4];
#pragma unroll
            for (int mt = 0; mt < 2; mt++) {
                uint32_t ad = aAddr + buf * bufB + (mt * 16 * LDSH + ks) * 2;
                asm volatile("ldmatrix.sync.aligned.m8n8.x4.shared.b16 {%0,%1,%2,%3},[%4];"
                             : "=r"(afr[mt][0]), "=r"(afr[mt][1]), "=r"(afr[mt][2]), "=r"(afr[mt][3])
                             : "r"(ad));
            }
#pragma unroll
            for (int p = 0; p < 4; p++) {
                uint32_t bd = bAddr + buf * bufB + (p * 16 * LDSH + ks) * 2;
                asm volatile("ldmatrix.sync.aligned.m8n8.x4.shared.b16 {%0,%1,%2,%3},[%4];"
                             : "=r"(bfr[p][0]), "=r"(bfr[p][1]), "=r"(bfr[p][2]), "=r"(bfr[p][3])
                             : "r"(bd));
            }
#pragma unroll
            for (int mt = 0; mt < 2; mt++)
#pragma unroll
                for (int p = 0; p < 4; p++)
#pragma unroll
                    for (int q = 0; q < 2; q++) {
                        float* c = acc[mt][p * 2 + q];
                        asm volatile(
                            "mma.sync.aligned.m16n8k16.row.col.f32.bf16.bf16.f32 "
                            "{%0,%1,%2,%3},{%4,%5,%6,%7},{%8,%9},{%0,%1,%2,%3};"
                            : "+f"(c[0]), "+f"(c[1]), "+f"(c[2]), "+f"(c[3])
                            : "r"(afr[mt][0]), "r"(afr[mt][1]), "r"(afr[mt][2]), "r"(afr[mt][3]),
                              "r"(bfr[p][q * 2]), "r"(bfr[p][q * 2 + 1]));
                    }
        }
        __syncthreads();
    }

    int g = lane >> 2, tg = lane & 3;
#pragma unroll
    for (int mt = 0; mt < 2; mt++) {
        int r0 = bm + wm + mt * 16 + g;
#pragma unroll
        for (int nt = 0; nt < 8; nt++) {
            int gc = bn + wn + nt * 8 + tg * 2;
            float b0 = bias[gc], b1 = bias[gc + 1];
            float* c = acc[mt][nt];
            if (r0 < M)
                *(bf162*)(C + (size_t)r0 * N + gc) =
                    __floats2bfloat162_rn(c[0] + b0, c[1] + b1);
            if (r0 + 8 < M)
                *(bf162*)(C + (size_t)(r0 + 8) * N + gc) =
                    __floats2bfloat162_rn(c[2] + b0, c[3] + b1);
        }
    }
}

// ---------------- fused MLP head (fc1 + relu + fc2) -----------------------------
__global__ void fc_fused(const float* __restrict__ pooled, const int* __restrict__ cnt,
                         const float* __restrict__ gfeat,
                         const float* __restrict__ W1, const float* __restrict__ b1,
                         const float* __restrict__ w2, const float* __restrict__ b2,
                         float* __restrict__ out) {
    __shared__ float s[HO2 + GF];
    __shared__ float red[128];
    int g = blockIdx.x, j = threadIdx.x;        // 128 threads
    float inv = 1.f / fmaxf((float)cnt[g], 1.f);
    for (int i = j; i < HO2; i += 128) s[i] = pooled[(size_t)g * HO2 + i] * inv;
    for (int i = j; i < GF;  i += 128) s[HO2 + i] = gfeat[(size_t)g * GF + i];
    __syncthreads();
    float acc = b1[j];
    for (int k = 0; k < HO2 + GF; k++) acc += s[k] * W1[k * 128 + j];
    float z = fmaxf(acc, 0.f);
    red[j] = z * w2[j];
    __syncthreads();
#pragma unroll
    for (int off = 64; off; off >>= 1) {
        if (j < off) red[j] += red[j + off];
        __syncthreads();
    }
    if (j == 0) out[g] = red[0] + b2[0];
}

// ---------------- host orchestration -------------------------------------------
static inline void* sym(const void* s) {
    void* p = nullptr;
    cudaGetSymbolAddress(&p, s);
    return p;
}

extern "C" void kernel_launch(void* const* d_in, const int* in_sizes, int n_in,
                              void* d_out, int out_size) {
    const float* x     = (const float*)d_in[0];
    const int*   ei    = (const int*)  d_in[1];
    const int*   batch = (const int*)  d_in[2];
    const float* gfeat = (const float*)d_in[3];
    const float* Wl1 = (const float*)d_in[4],  *bl1 = (const float*)d_in[5];
    const float* Wr1 = (const float*)d_in[6],  *br1 = (const float*)d_in[7];
    const float* att1 = (const float*)d_in[8], *bias1 = (const float*)d_in[9];
    const float* bn1g = (const float*)d_in[10], *bn1b = (const float*)d_in[11];
    const float* bn1m = (const float*)d_in[12], *bn1v = (const float*)d_in[13];
    const float* Wl2 = (const float*)d_in[14], *bl2 = (const float*)d_in[15];
    const float* Wr2 = (const float*)d_in[16], *br2 = (const float*)d_in[17];
    const float* att2 = (const float*)d_in[18], *bias2 = (const float*)d_in[19];
    const float* bn2g = (const float*)d_in[20], *bn2b = (const float*)d_in[21];
    const float* bn2m = (const float*)d_in[22], *bn2v = (const float*)d_in[23];
    const float* fc1w = (const float*)d_in[24], *fc1b = (const float*)d_in[25];
    const float* fc2w = (const float*)d_in[26], *fc2b = (const float*)d_in[27];
    float* out = (float*)d_out;

    bf16* xl1    = (bf16*)sym(g_xl1);
    bf16* xr1    = (bf16*)sym(g_xr1);
    bf16* h1     = (bf16*)sym(g_h1);
    bf16* xl2    = (bf16*)sym(g_xl2);
    bf16* xr2    = (bf16*)sym(g_xr2);
    bf16* wl2t   = (bf16*)sym(g_wl2t);
    bf16* wr2t   = (bf16*)sym(g_wr2t);
    float* pooled = (float*)sym(g_pooled);
    int*   cnt    = (int*)  sym(g_cnt);
    int* deg    = (int*)sym(g_deg);
    int* rowptr = (int*)sym(g_rowptr);
    int* cursor = (int*)sym(g_cursor);
    int* bsum   = (int*)sym(g_bsum);
    int* csrc   = (int*)sym(g_csrc);

    // ---- fused prologue: transform1(x4) + weight prep + degree count + zeroing --
    fused_pre<<<NB_PRE, 256>>>(x, Wl1, bl1, Wr1, br1, xl1, xr1,
                               Wl2, Wr2, wl2t, wr2t, ei, deg,
                               (float4*)pooled, cnt);

    // ---- CSR (scan reads deg+1 and self-resets deg) ----
    scan_local<<<SCAN_NB, SCAN_T>>>(deg, rowptr, bsum);
    scan_add2<<<SCAN_NB, SCAN_T>>>(rowptr, bsum, cursor);
    scatter_csr<<<(ET + 255) / 256, 256>>>(ei, cursor, csrc);

    // ---- layer 1 (2 warps per node, 2 heads each, EPL=4, SEG=16) ----
    gat_fused<4, 2, 16, false><<<(NN * 2 + 7) / 8, 256>>>(
        rowptr, csrc, xl1, xr1, att1, bias1, bn1g, bn1b, bn1m, bn1v,
        h1, nullptr, nullptr, nullptr);

    // ---- layer 2 transforms: both GEMMs in one launch (grid.z = 2) ----
    {
        dim3 grid((NN + 127) / 128, HO2 / 128, 2);
        gemm_bf16<<<grid, 256>>>(h1, wl2t, wr2t, bl2, br2, xl2, xr2,
                                 NN, HO2, HO1);
    }

    // ---- layer 2 fused (4 warps per node, 1 head each, EPL=4, SEG=32) ----
    gat_fused<4, 4, 32, true><<<(NN * 4 + 7) / 8, 256>>>(
        rowptr, csrc, xl2, xr2, att2, bias2, bn2g, bn2b, bn2m, bn2v,
        nullptr, pooled, cnt, batch);

    // ---- MLP head (fc1+relu+fc2 fused) ----
    fc_fused<<<GG, 128>>>(pooled, cnt, gfeat, fc1w, fc1b, fc2w, fc2b, out);
}

// round 16
// speedup vs baseline: 1.4410x; 1.4410x over previous
#include <cuda_runtime.h>
#include <cuda_bf16.h>
#include <stdint.h>
#include <math.h>

// Problem constants
#define NN 50000
#define EE 800000
#define ET (EE + NN)          // edges incl. self loops
#define GG 256
#define FF 9
#define GF 187
#define HH 4
#define O1 64
#define O2 128
#define HO1 (HH * O1)         // 256
#define HO2 (HH * O2)         // 512
#define BN_EPS 1e-5f
#define SM_EPS 1e-16f
#define SCAN_T 512
#define SCAN_NB ((NN + SCAN_T - 1) / SCAN_T)   // 98

typedef __nv_bfloat16  bf16;
typedef __nv_bfloat162 bf162;

// ---------------- scratch (device globals; no allocation allowed) -------------
__device__ bf16  g_xl1[(size_t)NN * HO1];
__device__ bf16  g_xr1[(size_t)NN * HO1];
__device__ bf16  g_h1 [(size_t)NN * HO1];
__device__ bf16  g_xl2[(size_t)NN * HO2];
__device__ bf16  g_xr2[(size_t)NN * HO2];
__device__ bf16  g_wl2t[(size_t)HO2 * HO1];   // [N=512][K=256] transposed bf16
__device__ bf16  g_wr2t[(size_t)HO2 * HO1];
__device__ float g_pooled[(size_t)GG * HO2];
__device__ int   g_cnt[GG];
// CSR scratch (g_deg starts zeroed; every graph replay leaves it zeroed)
__device__ int g_deg[NN];
__device__ int g_rowptr[NN + 1];
__device__ int g_cursor[NN];
__device__ int g_bsum[SCAN_NB];
__device__ int g_csrc[ET];

// ---------------- fused prologue -----------------------------------------------
#define NB_T1 NN                      // 50000 blocks
#define NB_CW 512                     // per weight matrix
#define NB_CD ((EE + 255) / 256)      // 3125
#define NB_ZP ((GG * HO2 / 4 + 255) / 256)   // 128
#define NB_PRE (NB_T1 + 2 * NB_CW + NB_CD + NB_ZP)

__global__ void __launch_bounds__(256)
fused_pre(const float* __restrict__ x,
          const float* __restrict__ Wl1, const float* __restrict__ bl1,
          const float* __restrict__ Wr1, const float* __restrict__ br1,
          bf16* __restrict__ xl1, bf16* __restrict__ xr1,
          const float* __restrict__ Wl2, const float* __restrict__ Wr2,
          bf16* __restrict__ wl2t, bf16* __restrict__ wr2t,
          const int* __restrict__ ei, int* __restrict__ deg,
          float4* __restrict__ pooled, int* __restrict__ cnt) {
    int b = blockIdx.x, t = threadIdx.x;
    if (b < NB_T1) {
        __shared__ float sx[FF];
        if (t < FF) sx[t] = x[b * FF + t];
        __syncthreads();
        float al = bl1[t], ar = br1[t];
#pragma unroll
        for (int k = 0; k < FF; k++) {
            float xv = sx[k];
            al += xv * Wl1[k * HO1 + t];
            ar += xv * Wr1[k * HO1 + t];
        }
        xl1[(size_t)b * HO1 + t] = __float2bfloat16(al);
        xr1[(size_t)b * HO1 + t] = __float2bfloat16(ar);
    } else if (b < NB_T1 + 2 * NB_CW) {
        int bb = b - NB_T1;
        const float* W = (bb < NB_CW) ? Wl2 : Wr2;
        bf16* Wt       = (bb < NB_CW) ? wl2t : wr2t;
        int n = bb % NB_CW;
        Wt[(size_t)n * HO1 + t] = __float2bfloat16(W[(size_t)t * HO2 + n]);
    } else if (b < NB_T1 + 2 * NB_CW + NB_CD) {
        int e = (b - NB_T1 - 2 * NB_CW) * 256 + t;
        if (e < EE) atomicAdd(&deg[ei[EE + e]], 1);
    } else {
        int i = (b - NB_T1 - 2 * NB_CW - NB_CD) * 256 + t;
        if (i < GG * HO2 / 4) pooled[i] = make_float4(0.f, 0.f, 0.f, 0.f);
        if (i < GG) cnt[i] = 0;
    }
}

// ---------------- CSR scan/scatter ----------------------------------------------
__global__ void scan_local(int* __restrict__ deg, int* __restrict__ rowptr,
                           int* __restrict__ bsum) {
    __shared__ int s[SCAN_T];
    int i = blockIdx.x * SCAN_T + threadIdx.x;
    int v = 0;
    if (i < NN) { v = deg[i] + 1; deg[i] = 0; }
    s[threadIdx.x] = v;
    __syncthreads();
    for (int off = 1; off < SCAN_T; off <<= 1) {
        int t = (threadIdx.x >= off) ? s[threadIdx.x - off] : 0;
        __syncthreads();
        s[threadIdx.x] += t;
        __syncthreads();
    }
    if (i < NN) rowptr[i] = s[threadIdx.x] - v;   // exclusive
    if (threadIdx.x == SCAN_T - 1) bsum[blockIdx.x] = s[threadIdx.x];
}
__global__ void scan_add2(int* __restrict__ rowptr, const int* __restrict__ bsum,
                          int* __restrict__ cursor) {
    __shared__ int sb[SCAN_NB];
    __shared__ int off;
    int b = blockIdx.x, t = threadIdx.x;
    if (t < SCAN_NB) sb[t] = bsum[t];
    __syncthreads();
    if (t == 0) {
        int acc = 0;
        for (int i = 0; i < b; i++) acc += sb[i];
        off = acc;
    }
    __syncthreads();
    int i = b * SCAN_T + t;
    if (i < NN) {
        int r = rowptr[i] + off;
        rowptr[i] = r;
        cursor[i] = r;
    }
    if (i == 0) rowptr[NN] = ET;
}
__global__ void scatter_csr(const int* __restrict__ ei, int* __restrict__ cursor,
                            int* __restrict__ csrc) {
    int e = blockIdx.x * blockDim.x + threadIdx.x;
    if (e >= ET) return;
    int s, d;
    if (e < EE) { s = ei[e]; d = ei[EE + e]; }
    else        { s = d = e - EE; }
    int p = atomicAdd(&cursor[d], 1);
    csrc[p] = s;
}

// ---------------- fused GAT layer (R12 structure, LOCKED) -----------------------
__device__ __forceinline__ void cvt4(const uint2 r, float* f) {
    float2 t;
    t = __bfloat1622float2(*(const bf162*)&r.x); f[0] = t.x; f[1] = t.y;
    t = __bfloat1622float2(*(const bf162*)&r.y); f[2] = t.x; f[3] = t.y;
}

template <int EPL, int PARTS, int SEG, bool POOL>   // EPL floats/lane (4)
__global__ void __launch_bounds__(256)
gat_fused(const int* __restrict__ rowptr, const int* __restrict__ csrc,
          const bf16* __restrict__ xl, const bf16* __restrict__ xr,
          const float* __restrict__ att, const float* __restrict__ bias,
          const float* __restrict__ bng, const float* __restrict__ bnb,
          const float* __restrict__ bnm, const float* __restrict__ bnv,
          bf16* __restrict__ out, float* __restrict__ pooled,
          int* __restrict__ cnt, const int* __restrict__ batch) {
    const int SL = EPL * 32;              // slice elems per warp
    const int HO = SL * PARTS;            // full row length
    int gw   = blockIdx.x * 8 + (threadIdx.x >> 5);
    int node = gw / PARTS;
    int part = gw % PARTS;
    int lane = threadIdx.x & 31;
    if (node >= NN) return;
    int    cbase = part * SL + lane * EPL;
    size_t nb    = (size_t)node * HO + cbase;

    float xr_r[EPL], att_r[EPL], S[EPL], v[EPL];
    cvt4(*(const uint2*)(xr + nb), xr_r);
    {
        float4 u = *(const float4*)(att + cbase);
        att_r[0] = u.x; att_r[1] = u.y; att_r[2] = u.z; att_r[3] = u.w;
    }
#pragma unroll
    for (int r = 0; r < EPL; r++) S[r] = 0.f;
    float den = 0.f;

    int beg = __ldg(rowptr + node), end = __ldg(rowptr + node + 1);
    int sn = __ldg(csrc + beg);
    uint2 rawn = *(const uint2*)(xl + (size_t)sn * HO + cbase);

    for (int e = beg; e < end; e++) {
        cvt4(rawn, v);
        if (e + 1 < end) {
            sn = __ldg(csrc + e + 1);
            rawn = *(const uint2*)(xl + (size_t)sn * HO + cbase);
        }
        float a = 0.f;
#pragma unroll
        for (int r = 0; r < EPL; r++) {
            float t = v[r] + xr_r[r];
            t = fmaxf(t, 0.2f * t);                 // leaky_relu(0.2)
            a = fmaf(t, att_r[r], a);
        }
        // segmented butterfly over the SEG-lane head group
        a += __shfl_xor_sync(0xFFFFFFFFu, a, 1);
        a += __shfl_xor_sync(0xFFFFFFFFu, a, 2);
        a += __shfl_xor_sync(0xFFFFFFFFu, a, 4);
        if constexpr (SEG >= 16) a += __shfl_xor_sync(0xFFFFFFFFu, a, 8);
        if constexpr (SEG == 32) a += __shfl_xor_sync(0xFFFFFFFFu, a, 16);
        float w = __expf(a);                        // bounded logits: no max needed
        den += w;
#pragma unroll
        for (int r = 0; r < EPL; r++) S[r] = fmaf(w, v[r], S[r]);
    }

    float inv = 1.f / (den + SM_EPS);
    float o[EPL];
#pragma unroll
    for (int r = 0; r < EPL; r++) {
        int c = cbase + r;
        float y = S[r] * inv + __ldg(bias + c);
        y = __ldg(bng + c) * (y - __ldg(bnm + c)) * rsqrtf(__ldg(bnv + c) + BN_EPS)
            + __ldg(bnb + c);
        o[r] = fmaxf(y, 0.f);
    }

    if constexpr (POOL) {
        int g = __ldg(batch + node);
        atomicAdd((float4*)(pooled + (size_t)g * HO + cbase),
                  make_float4(o[0], o[1], o[2], o[3]));
        if (part == 0 && lane == 0) atomicAdd(&cnt[g], 1);
    } else {
        uint2 raw;
        *(bf162*)&raw.x = __floats2bfloat162_rn(o[0], o[1]);
        *(bf162*)&raw.y = __floats2bfloat162_rn(o[2], o[3]);
        *(uint2*)(out + nb) = raw;
    }
}

// ---------------- bf16 tensor-core GEMM (cp.async double-buffered) -------------
#define LDSH 40
__device__ __forceinline__ void cp16(uint32_t dst, const void* src) {
    asm volatile("cp.async.cg.shared.global [%0], [%1], 16;\n" :: "r"(dst), "l"(src));
}
__global__ void __launch_bounds__(256)
gemm_bf16(const bf16* __restrict__ A,
          const bf16* __restrict__ Wt0, const bf16* __restrict__ Wt1,
          const float* __restrict__ bias0, const float* __restrict__ bias1,
          bf16* __restrict__ C0, bf16* __restrict__ C1,
          int M, int N, int K) {
    __shared__ __align__(16) bf16 As[2][128 * LDSH];
    __shared__ __align__(16) bf16 Bs[2][128 * LDSH];
    const bf16*  Wt   = blockIdx.z ? Wt1   : Wt0;
    const float* bias = blockIdx.z ? bias1 : bias0;
    bf16*        C    = blockIdx.z ? C1    : C0;

    int tid = threadIdx.x, warp = tid >> 5, lane = tid & 31;
    int bm = blockIdx.x * 128, bn = blockIdx.y * 128;
    int wm = (warp >> 1) * 32, wn = (warp & 1) * 64;
    int idx = lane & 7;
    int a_row = wm + ((lane >> 3) & 1) * 8 + idx;
    int a_col = (lane >> 4) * 8;
    int b_row = wn + (lane >> 4) * 8 + idx;
    int b_col = ((lane >> 3) & 1) * 8;
    uint32_t aBase = (uint32_t)__cvta_generic_to_shared(&As[0][0]);
    uint32_t bBase = (uint32_t)__cvta_generic_to_shared(&Bs[0][0]);
    uint32_t aAddr = aBase + (a_row * LDSH + a_col) * 2;
    uint32_t bAddr = bBase + (b_row * LDSH + b_col) * 2;
    const uint32_t bufB = 128 * LDSH * 2;

    float acc[2][8][4];
#pragma unroll
    for (int i = 0; i < 2; i++)
#pragma unroll
        for (int j = 0; j < 8; j++)
#pragma unroll
            for (int q = 0; q < 4; q++) acc[i][j][q] = 0.f;

    int lr = tid >> 2;            // 0..63
    int lc = (tid & 3) * 8;       // 0,8,16,24

    const int NT = K / 32;        // 8 k-tiles
    auto load_tile = [&](int buf, int k0) {
#pragma unroll
        for (int r = 0; r < 2; r++) {
            int row  = lr + r * 64;
            int grow = bm + row; if (grow > M - 1) grow = M - 1;
            cp16(aBase + buf * bufB + (row * LDSH + lc) * 2,
                 A + (size_t)grow * K + k0 + lc);
            cp16(bBase + buf * bufB + (row * LDSH + lc) * 2,
                 Wt + (size_t)(bn + row) * K + k0 + lc);
        }
        asm volatile("cp.async.commit_group;\n");
    };

    load_tile(0, 0);
    for (int kt = 0; kt < NT; kt++) {
        if (kt + 1 < NT) {
            load_tile((kt + 1) & 1, (kt + 1) * 32);
            asm volatile("cp.async.wait_group 1;\n");
        } else {
            asm volatile("cp.async.wait_group 0;\n");
        }
        __syncthreads();
        int buf = kt & 1;
#pragma unroll
        for (int ks = 0; ks < 32; ks += 16) {
            uint32_t afr[2][4], bfr[4][4];
#pragma unroll
            for (int mt = 0; mt < 2; mt++) {
                uint32_t ad = aAddr + buf * bufB + (mt * 16 * LDSH + ks) * 2;
                asm volatile("ldmatrix.sync.aligned.m8n8.x4.shared.b16 {%0,%1,%2,%3},[%4];"
                             : "=r"(afr[mt][0]), "=r"(afr[mt][1]), "=r"(afr[mt][2]), "=r"(afr[mt][3])
                             : "r"(ad));
            }
#pragma unroll
            for (int p = 0; p < 4; p++) {
                uint32_t bd = bAddr + buf * bufB + (p * 16 * LDSH + ks) * 2;
                asm volatile("ldmatrix.sync.aligned.m8n8.x4.shared.b16 {%0,%1,%2,%3},[%4];"
                             : "=r"(bfr[p][0]), "=r"(bfr[p][1]), "=r"(bfr[p][2]), "=r"(bfr[p][3])
                             : "r"(bd));
            }
#pragma unroll
            for (int mt = 0; mt < 2; mt++)
#pragma unroll
                for (int p = 0; p < 4; p++)
#pragma unroll
                    for (int q = 0; q < 2; q++) {
                        float* c = acc[mt][p * 2 + q];
                        asm volatile(
                            "mma.sync.aligned.m16n8k16.row.col.f32.bf16.bf16.f32 "
                            "{%0,%1,%2,%3},{%4,%5,%6,%7},{%8,%9},{%0,%1,%2,%3};"
                            : "+f"(c[0]), "+f"(c[1]), "+f"(c[2]), "+f"(c[3])
                            : "r"(afr[mt][0]), "r"(afr[mt][1]), "r"(afr[mt][2]), "r"(afr[mt][3]),
                              "r"(bfr[p][q * 2]), "r"(bfr[p][q * 2 + 1]));
                    }
        }
        __syncthreads();
    }

    int g = lane >> 2, tg = lane & 3;
#pragma unroll
    for (int mt = 0; mt < 2; mt++) {
        int r0 = bm + wm + mt * 16 + g;
#pragma unroll
        for (int nt = 0; nt < 8; nt++) {
            int gc = bn + wn + nt * 8 + tg * 2;
            float b0 = bias[gc], b1 = bias[gc + 1];
            float* c = acc[mt][nt];
            if (r0 < M)
                *(bf162*)(C + (size_t)r0 * N + gc) =
                    __floats2bfloat162_rn(c[0] + b0, c[1] + b1);
            if (r0 + 8 < M)
                *(bf162*)(C + (size_t)(r0 + 8) * N + gc) =
                    __floats2bfloat162_rn(c[2] + b0, c[3] + b1);
        }
    }
}

// ---------------- fused MLP head (fc1 + relu + fc2) -----------------------------
__global__ void fc_fused(const float* __restrict__ pooled, const int* __restrict__ cnt,
                         const float* __restrict__ gfeat,
                         const float* __restrict__ W1, const float* __restrict__ b1,
                         const float* __restrict__ w2, const float* __restrict__ b2,
                         float* __restrict__ out) {
    __shared__ float s[HO2 + GF];
    __shared__ float red[128];
    int g = blockIdx.x, j = threadIdx.x;        // 128 threads
    float inv = 1.f / fmaxf((float)cnt[g], 1.f);
    for (int i = j; i < HO2; i += 128) s[i] = pooled[(size_t)g * HO2 + i] * inv;
    for (int i = j; i < GF;  i += 128) s[HO2 + i] = gfeat[(size_t)g * GF + i];
    __syncthreads();
    float acc = b1[j];
    for (int k = 0; k < HO2 + GF; k++) acc += s[k] * W1[k * 128 + j];
    float z = fmaxf(acc, 0.f);
    red[j] = z * w2[j];
    __syncthreads();
#pragma unroll
    for (int off = 64; off; off >>= 1) {
        if (j < off) red[j] += red[j + off];
        __syncthreads();
    }
    if (j == 0) out[g] = red[0] + b2[0];
}

// ---------------- host orchestration -------------------------------------------
static inline void* sym(const void* s) {
    void* p = nullptr;
    cudaGetSymbolAddress(&p, s);
    return p;
}

extern "C" void kernel_launch(void* const* d_in, const int* in_sizes, int n_in,
                              void* d_out, int out_size) {
    const float* x     = (const float*)d_in[0];
    const int*   ei    = (const int*)  d_in[1];
    const int*   batch = (const int*)  d_in[2];
    const float* gfeat = (const float*)d_in[3];
    const float* Wl1 = (const float*)d_in[4],  *bl1 = (const float*)d_in[5];
    const float* Wr1 = (const float*)d_in[6],  *br1 = (const float*)d_in[7];
    const float* att1 = (const float*)d_in[8], *bias1 = (const float*)d_in[9];
    const float* bn1g = (const float*)d_in[10], *bn1b = (const float*)d_in[11];
    const float* bn1m = (const float*)d_in[12], *bn1v = (const float*)d_in[13];
    const float* Wl2 = (const float*)d_in[14], *bl2 = (const float*)d_in[15];
    const float* Wr2 = (const float*)d_in[16], *br2 = (const float*)d_in[17];
    const float* att2 = (const float*)d_in[18], *bias2 = (const float*)d_in[19];
    const float* bn2g = (const float*)d_in[20], *bn2b = (const float*)d_in[21];
    const float* bn2m = (const float*)d_in[22], *bn2v = (const float*)d_in[23];
    const float* fc1w = (const float*)d_in[24], *fc1b = (const float*)d_in[25];
    const float* fc2w = (const float*)d_in[26], *fc2b = (const float*)d_in[27];
    float* out = (float*)d_out;

    bf16* xl1    = (bf16*)sym(g_xl1);
    bf16* xr1    = (bf16*)sym(g_xr1);
    bf16* h1     = (bf16*)sym(g_h1);
    bf16* xl2    = (bf16*)sym(g_xl2);
    bf16* xr2    = (bf16*)sym(g_xr2);
    bf16* wl2t   = (bf16*)sym(g_wl2t);
    bf16* wr2t   = (bf16*)sym(g_wr2t);
    float* pooled = (float*)sym(g_pooled);
    int*   cnt    = (int*)  sym(g_cnt);
    int* deg    = (int*)sym(g_deg);
    int* rowptr = (int*)sym(g_rowptr);
    int* cursor = (int*)sym(g_cursor);
    int* bsum   = (int*)sym(g_bsum);
    int* csrc   = (int*)sym(g_csrc);

    // ---- fused prologue: transform1 + weight prep + degree count + zeroing ----
    fused_pre<<<NB_PRE, 256>>>(x, Wl1, bl1, Wr1, br1, xl1, xr1,
                               Wl2, Wr2, wl2t, wr2t, ei, deg,
                               (float4*)pooled, cnt);

    // ---- CSR (scan reads deg+1 and self-resets deg) ----
    scan_local<<<SCAN_NB, SCAN_T>>>(deg, rowptr, bsum);
    scan_add2<<<SCAN_NB, SCAN_T>>>(rowptr, bsum, cursor);
    scatter_csr<<<(ET + 255) / 256, 256>>>(ei, cursor, csrc);

    // ---- layer 1 (2 warps per node, 2 heads each, EPL=4, SEG=16) ----
    gat_fused<4, 2, 16, false><<<(NN * 2 + 7) / 8, 256>>>(
        rowptr, csrc, xl1, xr1, att1, bias1, bn1g, bn1b, bn1m, bn1v,
        h1, nullptr, nullptr, nullptr);

    // ---- layer 2 transforms: both GEMMs in one launch (grid.z = 2) ----
    {
        dim3 grid((NN + 127) / 128, HO2 / 128, 2);
        gemm_bf16<<<grid, 256>>>(h1, wl2t, wr2t, bl2, br2, xl2, xr2,
                                 NN, HO2, HO1);
    }

    // ---- layer 2 fused (4 warps per node, 1 head each, EPL=4, SEG=32) ----
    gat_fused<4, 4, 32, true><<<(NN * 4 + 7) / 8, 256>>>(
        rowptr, csrc, xl2, xr2, att2, bias2, bn2g, bn2b, bn2m, bn2v,
        nullptr, pooled, cnt, batch);

    // ---- MLP head (fc1+relu+fc2 fused) ----
    fc_fused<<<GG, 128>>>(pooled, cnt, gfeat, fc1w, fc1b, fc2w, fc2b, out);
}